// round 16
// baseline (speedup 1.0000x reference)
#include <cuda_runtime.h>
#include <cuda_bf16.h>
#include <math.h>
#include <stdint.h>

#define NN   20000
#define EE   320000
#define DIN  128
#define HH   256
#define LL   2
#define GG   32
#define NREL 6

// ---------------- device scratch ----------------
__device__ float g_accb[2 * NN * HH];
__device__ uint8_t g_tmpf[NREL * NN * HH];          // neighbor GEMM outputs (fp8 e4m3)
__device__ __nv_bfloat16 g_xb[2 * NN * HH];         // bf16 feature/residual carrier
__device__ __nv_bfloat16 g_inb[2 * NN * DIN];
__device__ __nv_bfloat16 g_web[2 * HH * DIN];
__device__ __nv_bfloat16 g_wcat[LL * 2 * 1024 * HH];
__device__ float g_blsum[LL * 2 * HH];
__device__ int   g_deg[NREL][NN];
__device__ int   g_rowptr[NREL][NN + 1];
__device__ int   g_cursor[NREL][NN];
__device__ int   g_col[NREL][EE];
struct ZeroBlk {
    float stats[LL * 2 * 2 * HH];
    float pool[2 * GG * HH];
    int   pcnt[2 * GG];
};
__device__ ZeroBlk g_z;
__device__ int g_is64;

// ---------------- helpers ----------------
__device__ __forceinline__ int idx_at(const void* p, long long i, int is64) {
    return is64 ? (int)((const long long*)p)[i] : ((const int*)p)[i];
}
__device__ __forceinline__ uint32_t smem_u32(const void* p) {
    uint32_t a;
    asm("{ .reg .u64 t; cvta.to.shared.u64 t, %1; cvt.u32.u64 %0, t; }" : "=r"(a) : "l"(p));
    return a;
}
__device__ __forceinline__ void ldm_x4(uint32_t* r, uint32_t addr) {
    asm volatile("ldmatrix.sync.aligned.m8n8.x4.shared.b16 {%0,%1,%2,%3}, [%4];"
                 : "=r"(r[0]), "=r"(r[1]), "=r"(r[2]), "=r"(r[3]) : "r"(addr));
}
__device__ __forceinline__ void mma_bf16(float* c, const uint32_t* a, const uint32_t* b) {
    asm volatile("mma.sync.aligned.m16n8k16.row.col.f32.bf16.bf16.f32 "
                 "{%0,%1,%2,%3}, {%4,%5,%6,%7}, {%8,%9}, {%0,%1,%2,%3};"
                 : "+f"(c[0]), "+f"(c[1]), "+f"(c[2]), "+f"(c[3])
                 : "r"(a[0]), "r"(a[1]), "r"(a[2]), "r"(a[3]), "r"(b[0]), "r"(b[1]));
}
__device__ __forceinline__ void cp16(uint32_t dst, const void* src, int nbytes) {
    asm volatile("cp.async.cg.shared.global [%0], [%1], 16, %2;"
                 :: "r"(dst), "l"(src), "r"(nbytes));
}
__device__ __forceinline__ unsigned short pack_e4m3x2(float v0, float v1) {
    unsigned short pk;
    asm("cvt.rn.satfinite.e4m3x2.f32 %0, %1, %2;" : "=h"(pk) : "f"(v1), "f"(v0));
    return pk;
}
__device__ __forceinline__ void addv8(float* s, uint2 v) {
#pragma unroll
    for (int w = 0; w < 2; w++) {
        uint32_t word = w ? v.y : v.x;
#pragma unroll
        for (int h = 0; h < 2; h++) {
            unsigned short pk = (unsigned short)(word >> (h * 16));
            uint32_t f16p;
            asm("cvt.rn.f16x2.e4m3x2 %0, %1;" : "=r"(f16p) : "h"(pk));
            __half2 hh = *reinterpret_cast<__half2*>(&f16p);
            float2 f = __half22float2(hh);
            int bi = w * 4 + h * 2;
            s[bi] += f.x;
            s[bi + 1] += f.y;
        }
    }
}

// ---------------- prep: detect + weights + input split + edge histogram ----------------
__global__ void k_prep(const unsigned int* __restrict__ e,
                       const float* __restrict__ xv, const float* __restrict__ xp,
                       const float* __restrict__ We, const float* __restrict__ Wl,
                       const float* __restrict__ Wr, const float* __restrict__ bl) {
    const int grp[2][3] = {{0, 1, 3}, {2, 4, 5}};
    int gid = blockIdx.x * blockDim.x + threadIdx.x;

    // per-block dtype detection (8KB L2-hot sample) so hist needs no prior kernel
    __shared__ int s_any;
    if (threadIdx.x == 0) s_any = 0;
    __syncthreads();
    unsigned int v = 0;
    for (int i = threadIdx.x; i < 2048; i += blockDim.x)
        v |= e[(long long)i * 1874 + 1];
    if (v) s_any = 1;
    __syncthreads();
    int is64 = s_any ? 0 : 1;
    if (blockIdx.x == 0 && threadIdx.x == 0) g_is64 = is64;

    if (gid < NREL * EE) {                     // edge histogram (fused)
        int r = gid / EE, ei = gid - r * EE;
        int dst = idx_at(e, ((long long)r * 2 + 1) * EE + ei, is64);
        atomicAdd(&g_deg[r][dst], 1);
    }
    if (gid < 2 * NN * DIN) {                  // input split
        float s = (gid < NN * DIN) ? xv[gid] : xp[gid - NN * DIN];
        g_inb[gid] = __float2bfloat16(s);
    }
    if (gid < 2 * HH * DIN) {                  // emb weights -> [t][n][k]
        int t = gid >> 15, rem = gid & 32767, n = rem >> 7, k = rem & 127;
        g_web[t * HH * DIN + n * DIN + k] =
            __float2bfloat16(We[((long long)t * DIN + k) * HH + n]);
    }
    if (gid < LL * 2 * 1024 * HH) {            // merged layer B
        int lt = gid >> 18, rem = gid & 0x3FFFF, row = rem >> 8, k = rem & 255;
        int layer = lt >> 1, t = lt & 1;
        float w;
        if (row < 256) {
            int n = row;
            const float* W = Wr + (long long)layer * NREL * HH * HH;
            w = W[(long long)grp[t][0] * HH * HH + k * HH + n] +
                W[(long long)grp[t][1] * HH * HH + k * HH + n] +
                W[(long long)grp[t][2] * HH * HH + k * HH + n];
        } else {
            int q = (row - 256) >> 8, n = row & 255;
            int rel = t * 3 + q;
            w = Wl[(((long long)layer * NREL + rel) * HH + k) * HH + n];
        }
        g_wcat[(long long)lt * 1024 * HH + row * HH + k] = __float2bfloat16(w);
    }
    if (gid < LL * 2 * HH) {                   // summed biases
        int lt = gid >> 8, c = gid & 255;
        int layer = lt >> 1, t = lt & 1;
        const float* b = bl + (long long)layer * NREL * HH;
        g_blsum[lt * HH + c] = b[grp[t][0] * HH + c] + b[grp[t][1] * HH + c] +
                               b[grp[t][2] * HH + c];
    }
}

// ---------------- CSR scan ----------------
__global__ void __launch_bounds__(1024) k_scan() {
    int r = blockIdx.x;
    const int PER = 20;
    int tid = threadIdx.x;
    int lane = tid & 31, wid = tid >> 5;
    int start = tid * PER;
    int loc[PER];
    int sum = 0;
#pragma unroll
    for (int i = 0; i < PER; i++) {
        int idx = start + i;
        int v = (idx < NN) ? g_deg[r][idx] : 0;
        loc[i] = sum;
        sum += v;
    }
    __shared__ int wsum[32];
    int incl = sum;
#pragma unroll
    for (int o = 1; o < 32; o <<= 1) {
        int x = __shfl_up_sync(0xffffffffu, incl, o);
        if (lane >= o) incl += x;
    }
    if (lane == 31) wsum[wid] = incl;
    __syncthreads();
    if (wid == 0) {
        int v = wsum[lane];
#pragma unroll
        for (int o = 1; o < 32; o <<= 1) {
            int x = __shfl_up_sync(0xffffffffu, v, o);
            if (lane >= o) v += x;
        }
        wsum[lane] = v;
    }
    __syncthreads();
    int prefix = incl - sum + (wid ? wsum[wid - 1] : 0);
#pragma unroll
    for (int i = 0; i < PER; i++) {
        int idx = start + i;
        if (idx < NN) {
            int ex = prefix + loc[i];
            g_rowptr[r][idx] = ex;
            g_cursor[r][idx] = ex;
        }
    }
    if (tid == 1023) g_rowptr[r][NN] = prefix + sum;
}

// ---------------- CSR fill + pooled-count (fused) ----------------
__global__ void k_fillp(const void* __restrict__ edge,
                        const void* __restrict__ bv, const void* __restrict__ bp,
                        int* __restrict__ pcnt) {
    int is64 = g_is64;
    int gid = blockIdx.x * blockDim.x + threadIdx.x;
    if (gid < NREL * EE) {
        int r = gid / EE, e = gid - r * EE;
        int src = idx_at(edge, ((long long)r * 2 + 0) * EE + e, is64);
        int dst = idx_at(edge, ((long long)r * 2 + 1) * EE + e, is64);
        int slot = atomicAdd(&g_cursor[r][dst], 1);
        g_col[r][slot] = src;
    } else {
        int q = gid - NREL * EE;
        if (q < 2 * NN) {
            int t = q / NN, i = q - t * NN;
            int g = t ? idx_at(bp, i, is64) : idx_at(bv, i, is64);
            atomicAdd(&pcnt[t * GG + g], 1);
        }
    }
}

// ---------------- HMMA GEMM (bf16x1, BK=64, cp.async double-buffered) ----------------
#define SPAD2 72
#define BUFB (128 * SPAD2 * 2)
#define SMEM_G (4 * BUFB)

__global__ void __launch_bounds__(256, 2) k_gemm(
    const __nv_bfloat16* __restrict__ A0, long long aStr,
    const __nv_bfloat16* __restrict__ B0, long long bStr,
    float* __restrict__ Cf0, long long cfStr,
    const float* __restrict__ bias0, int biasStr,
    __nv_bfloat16* __restrict__ Xb0, long long xbzStr,
    uint8_t* __restrict__ F80, long long f8zStr, long long f8Stride,
    int selfN, int dualOut, int M, int K)
{
    extern __shared__ __nv_bfloat16 sm[];
    int z = blockIdx.z;
    const __nv_bfloat16* A = A0 + (long long)z * aStr;
    const __nv_bfloat16* B = B0 + (long long)z * bStr;
    float* Cf = Cf0 ? Cf0 + (long long)z * cfStr : nullptr;
    const float* bias = bias0 ? bias0 + (long long)z * biasStr : nullptr;
    __nv_bfloat16* Xb = Xb0 ? Xb0 + (long long)z * xbzStr : nullptr;
    uint8_t* F8z = F80 ? F80 + (long long)z * f8zStr : nullptr;

    int tid = threadIdx.x, wid = tid >> 5, lane = tid & 31;
    long long bm = (long long)blockIdx.x * 128;
    int nb = blockIdx.y * 128;
    int wm = (wid & 3) * 32;
    int wn = (wid >> 2) * 64;
    uint32_t sbA = smem_u32(sm);
    uint32_t sbB = sbA + 2 * BUFB;

    float acc[2][8][4];
#pragma unroll
    for (int i = 0; i < 2; i++)
#pragma unroll
        for (int j = 0; j < 8; j++)
#pragma unroll
            for (int q = 0; q < 4; q++) acc[i][j][q] = 0.0f;

    int a_row = (lane & 7) + ((lane >> 3) & 1) * 8;
    int a_col = (lane >> 4) * 8;
    int b_row = lane & 7;
    int b_col = (lane >> 3) * 8;
    int nch = K >> 6;

#define ISSUE_STAGE(c, buf) do {                                                    \
        _Pragma("unroll")                                                           \
        for (int i = tid; i < 1024; i += 256) {                                     \
            int row = i >> 3, seg = (i & 7) << 3;                                   \
            uint32_t so = (buf) * BUFB + (uint32_t)(row * SPAD2 + seg) * 2;         \
            int av = (bm + row < M) ? 16 : 0;                                       \
            const __nv_bfloat16* ga = A + ((bm + row < M) ?                         \
                                           ((bm + row) * K + (c) * 64 + seg) : 0);  \
            const __nv_bfloat16* gb = B + ((long long)(nb + row) * K + (c) * 64 + seg); \
            cp16(sbA + so, ga, av);                                                 \
            cp16(sbB + so, gb, 16);                                                 \
        }                                                                           \
        asm volatile("cp.async.commit_group;");                                     \
    } while (0)

    ISSUE_STAGE(0, 0);
    for (int c = 0; c < nch; c++) {
        if (c + 1 < nch) {
            ISSUE_STAGE(c + 1, (c + 1) & 1);
            asm volatile("cp.async.wait_group 1;");
        } else {
            asm volatile("cp.async.wait_group 0;");
        }
        __syncthreads();

        uint32_t bA = sbA + (c & 1) * BUFB, bB = sbB + (c & 1) * BUFB;
#pragma unroll
        for (int half = 0; half < 2; half++) {
            uint32_t bf[8][4];
#pragma unroll
            for (int nt = 0; nt < 8; nt++)
                ldm_x4(bf[nt], bB + (uint32_t)((wn + nt * 8 + b_row) * SPAD2 +
                                               half * 32 + b_col) * 2);
#pragma unroll
            for (int ks = 0; ks < 2; ks++) {
                uint32_t af[2][4];
#pragma unroll
                for (int mt = 0; mt < 2; mt++)
                    ldm_x4(af[mt], bA + (uint32_t)((wm + mt * 16 + a_row) * SPAD2 +
                                                   half * 32 + ks * 16 + a_col) * 2);
#pragma unroll
                for (int mt = 0; mt < 2; mt++)
#pragma unroll
                    for (int nt = 0; nt < 8; nt++)
                        mma_bf16(acc[mt][nt], af[mt], &bf[nt][ks * 2]);
            }
        }
        __syncthreads();
    }
#undef ISSUE_STAGE

    // ---- epilogue ----
    bool isSelf = (int)blockIdx.y < selfN;
    uint8_t* F8 = (!isSelf && F8z) ? (F8z + (long long)((blockIdx.y >> 1) - 1) * f8Stride) : nullptr;
    int gidr = lane >> 2, tig = lane & 3;
#pragma unroll
    for (int mt = 0; mt < 2; mt++) {
        long long r0 = bm + wm + mt * 16 + gidr;
        long long r1 = r0 + 8;
#pragma unroll
        for (int nt = 0; nt < 8; nt++) {
            int col = (blockIdx.y & 1) * 128 + wn + nt * 8 + tig * 2;
            float b0 = 0.f, b1 = 0.f;
            if (isSelf && bias) { b0 = bias[col]; b1 = bias[col + 1]; }
            if (r0 < M) {
                float v0 = acc[mt][nt][0] + b0, v1 = acc[mt][nt][1] + b1;
                if (isSelf) {
                    if (Cf) *(float2*)&Cf[r0 * 256 + col] = make_float2(v0, v1);
                    if (dualOut) *(__nv_bfloat162*)&Xb[r0 * 256 + col] = __floats2bfloat162_rn(v0, v1);
                } else {
                    *(unsigned short*)&F8[r0 * 256 + col] = pack_e4m3x2(v0, v1);
                }
            }
            if (r1 < M) {
                float v2 = acc[mt][nt][2] + b0, v3 = acc[mt][nt][3] + b1;
                if (isSelf) {
                    if (Cf) *(float2*)&Cf[r1 * 256 + col] = make_float2(v2, v3);
                    if (dualOut) *(__nv_bfloat162*)&Xb[r1 * 256 + col] = __floats2bfloat162_rn(v2, v3);
                } else {
                    *(unsigned short*)&F8[r1 * 256 + col] = pack_e4m3x2(v2, v3);
                }
            }
        }
    }
}

// ---------------- gather-mean aggregation (fp8 source) + fused BN stats ----------------
__global__ void k_agg(float* __restrict__ acc0, float* __restrict__ stats0) {
    __shared__ float bsum[HH], bsq[HH];
    int tid = threadIdx.x;
    int t = blockIdx.y;
    for (int i = tid; i < HH; i += 256) { bsum[i] = 0.f; bsq[i] = 0.f; }
    __syncthreads();

    int w = (blockIdx.x * blockDim.x + tid) >> 5;
    int lane = tid & 31;
    const int grp[2][3] = {{0, 1, 3}, {2, 4, 5}};
    float* acc = acc0 + (long long)t * NN * HH;
    float* stats = stats0 + t * 2 * HH;

    if (w < NN) {
        float s3[8] = {0.f, 0.f, 0.f, 0.f, 0.f, 0.f, 0.f, 0.f};
#pragma unroll
        for (int q = 0; q < 3; q++) {
            int r = grp[t][q];
            int b = g_rowptr[r][w], e = g_rowptr[r][w + 1];
            float s[8] = {0.f, 0.f, 0.f, 0.f, 0.f, 0.f, 0.f, 0.f};
            const uint2* base = (const uint2*)(g_tmpf + (long long)r * NN * HH);
            for (int j0 = b; j0 < e; j0 += 32) {
                int n = min(32, e - j0);
                int myc = (lane < n) ? g_col[r][j0 + lane] : 0;
                int k = 0;
                for (; k + 3 < n; k += 4) {
                    int c0 = __shfl_sync(0xffffffffu, myc, k);
                    int c1 = __shfl_sync(0xffffffffu, myc, k + 1);
                    int c2 = __shfl_sync(0xffffffffu, myc, k + 2);
                    int c3 = __shfl_sync(0xffffffffu, myc, k + 3);
                    uint2 v0 = base[(long long)c0 * 32 + lane];
                    uint2 v1 = base[(long long)c1 * 32 + lane];
                    uint2 v2 = base[(long long)c2 * 32 + lane];
                    uint2 v3 = base[(long long)c3 * 32 + lane];
                    addv8(s, v0); addv8(s, v1); addv8(s, v2); addv8(s, v3);
                }
                for (; k < n; k++) {
                    int c0 = __shfl_sync(0xffffffffu, myc, k);
                    uint2 v0 = base[(long long)c0 * 32 + lane];
                    addv8(s, v0);
                }
            }
            float inv = (e > b) ? 1.0f / (float)(e - b) : 0.0f;
#pragma unroll
            for (int u = 0; u < 8; u++) s3[u] = fmaf(s[u], inv, s3[u]);
        }
        float4* arow = (float4*)(acc + (long long)w * HH + lane * 8);
        float4 o0 = arow[0], o1 = arow[1];
        float fin[8] = {o0.x + s3[0], o0.y + s3[1], o0.z + s3[2], o0.w + s3[3],
                        o1.x + s3[4], o1.y + s3[5], o1.z + s3[6], o1.w + s3[7]};
        arow[0] = make_float4(fin[0], fin[1], fin[2], fin[3]);
        arow[1] = make_float4(fin[4], fin[5], fin[6], fin[7]);
#pragma unroll
        for (int u = 0; u < 8; u++) {
            atomicAdd(&bsum[lane * 8 + u], fin[u]);
            atomicAdd(&bsq[lane * 8 + u], fin[u] * fin[u]);
        }
    }
    __syncthreads();
    for (int i = tid; i < HH; i += 256) {
        atomicAdd(&stats[i], bsum[i]);
        atomicAdd(&stats[HH + i], bsq[i]);
    }
}

// ---------------- batchnorm apply (non-final layers, bf16 carrier) ----------------
__global__ void k_bnapply(const float* __restrict__ acc0,
                          __nv_bfloat16* __restrict__ xb0,
                          const float* __restrict__ st0, const float* __restrict__ gamma0,
                          const float* __restrict__ beta0, int resid) {
    int t = blockIdx.y;
    long long off = (long long)t * NN * HH;
    const float* acc = acc0 + off;
    __nv_bfloat16* xb = xb0 + off;
    const float* st = st0 + t * 2 * HH;
    const float* gamma = gamma0 + t * HH;
    const float* beta  = beta0 + t * HH;
    int c = threadIdx.x;
    float meanA = st[c] * (1.0f / NN);
    float varA  = st[HH + c] * (1.0f / NN) - meanA * meanA;
    float varX  = varA * (1.0f / 9.0f);
    float rs    = rsqrtf(varX + 1e-5f);
    float scale = gamma[c] * rs * (1.0f / 3.0f);
    float shift = beta[c] - meanA * scale;
    for (int r = blockIdx.x; r < NN; r += gridDim.x) {
        long long i = (long long)r * HH + c;
        float y = fmaxf(fmaf(acc[i], scale, shift), 0.0f);
        float xn = resid ? (__bfloat162float(xb[i]) + y) : y;
        xb[i] = __float2bfloat16(xn);
    }
}

// ---------------- final layer: BN + residual(bf16) + mean pool, fused ----------------
__global__ void k_bnpool(const float* __restrict__ acc0, const __nv_bfloat16* __restrict__ xb0,
                         const float* __restrict__ st0, const float* __restrict__ gamma0,
                         const float* __restrict__ beta0,
                         const void* __restrict__ bv, const void* __restrict__ bp,
                         float* __restrict__ pool0) {
    int is64 = g_is64;
    int t = blockIdx.y;
    long long off = (long long)t * NN * HH;
    const float* acc = acc0 + off;
    const __nv_bfloat16* xb = xb0 + off;
    const float* st = st0 + t * 2 * HH;
    const void* batch = t ? bp : bv;
    float* pool = pool0 + t * GG * HH;
    int c = threadIdx.x;
    float meanA = st[c] * (1.0f / NN);
    float varA  = st[HH + c] * (1.0f / NN) - meanA * meanA;
    float rs    = rsqrtf(varA * (1.0f / 9.0f) + 1e-5f);
    float scale = gamma0[t * HH + c] * rs * (1.0f / 3.0f);
    float shift = beta0[t * HH + c] - meanA * scale;

    int r0 = blockIdx.x * 64;
    int r1 = min(r0 + 64, NN);
    float local = 0.f;
    int gprev = -1;
    for (int r = r0; r < r1; r++) {
        int g = idx_at(batch, r, is64);
        if (g != gprev) {
            if (gprev >= 0) atomicAdd(&pool[gprev * HH + c], local);
            local = 0.f;
            gprev = g;
        }
        long long i = (long long)r * HH + c;
        float y = fmaxf(fmaf(acc[i], scale, shift), 0.0f);
        local += __bfloat162float(xb[i]) + y;
    }
    if (gprev >= 0) atomicAdd(&pool[gprev * HH + c], local);
}

// ---------------- head ----------------
__global__ void k_final(const float* __restrict__ Wo, const float* __restrict__ bo,
                        const float* __restrict__ pool, const int* __restrict__ pcnt,
                        float* __restrict__ out) {
    int g = threadIdx.x >> 5, lane = threadIdx.x & 31;
    if (g >= GG) return;
    float cv = (float)max(pcnt[g], 1);
    float cp = (float)max(pcnt[GG + g], 1);
    float s = 0.f;
    for (int c = lane; c < HH; c += 32)
        s += pool[g * HH + c] / cv * Wo[c] + pool[GG * HH + g * HH + c] / cp * Wo[HH + c];
#pragma unroll
    for (int off = 16; off; off >>= 1) s += __shfl_down_sync(0xffffffffu, s, off);
    if (lane == 0) out[g] = 1.0f / (1.0f + expf(-(s + bo[0])));
}

// ---------------- launcher ----------------
extern "C" void kernel_launch(void* const* d_in, const int* in_sizes, int n_in,
                              void* d_out, int out_size) {
    const float* x_vuln  = (const float*)d_in[0];
    const float* x_patch = (const float*)d_in[1];
    const float* W_emb   = (const float*)d_in[2];
    const float* b_emb   = (const float*)d_in[3];
    const float* W_l     = (const float*)d_in[4];
    const float* b_l     = (const float*)d_in[5];
    const float* W_r     = (const float*)d_in[6];
    const float* gamma   = (const float*)d_in[7];
    const float* beta    = (const float*)d_in[8];
    const float* W_out   = (const float*)d_in[9];
    const float* b_out   = (const float*)d_in[10];
    const void* edge     = d_in[11];
    const void* batch_v  = d_in[12];
    const void* batch_p  = d_in[13];
    float* out = (float*)d_out;

    void* p;
    cudaGetSymbolAddress(&p, g_accb);  float* a0 = (float*)p;
    cudaGetSymbolAddress(&p, g_tmpf);  uint8_t* tmpf = (uint8_t*)p;
    cudaGetSymbolAddress(&p, g_xb);    __nv_bfloat16* xb = (__nv_bfloat16*)p;
    cudaGetSymbolAddress(&p, g_inb);   __nv_bfloat16* inb = (__nv_bfloat16*)p;
    cudaGetSymbolAddress(&p, g_web);   __nv_bfloat16* web = (__nv_bfloat16*)p;
    cudaGetSymbolAddress(&p, g_wcat);  __nv_bfloat16* wcat = (__nv_bfloat16*)p;
    cudaGetSymbolAddress(&p, g_blsum); float* bls = (float*)p;
    cudaGetSymbolAddress(&p, g_deg);   void* degp = p;
    cudaGetSymbolAddress(&p, g_z);     void* zbase = p;
    float* zstats = (float*)zbase;
    float* zpool  = zstats + LL * 2 * 2 * HH;
    int*   zpcnt  = (int*)(zpool + 2 * GG * HH);

    cudaFuncSetAttribute(k_gemm, cudaFuncAttributeMaxDynamicSharedMemorySize, SMEM_G);

    cudaMemsetAsync(degp, 0, sizeof(int) * NREL * NN, 0);
    cudaMemsetAsync(zbase, 0, sizeof(ZeroBlk), 0);

    // prep (detect + weights + split + hist), scan, fill+pcnt
    k_prep<<<20000, 256>>>((const unsigned int*)edge, x_vuln, x_patch, W_emb, W_l, W_r, b_l);
    k_scan<<<NREL, 1024>>>();
    k_fillp<<<(NREL * EE + 2 * NN + 255) / 256, 256>>>(edge, batch_v, batch_p, zpcnt);

    const int MB = (NN + 127) / 128;
    size_t xs = (size_t)NN * HH;
    // embedding GEMMs (K=128): bf16 xb output only (fp32 out is dead)
    k_gemm<<<dim3(MB, 2, 2), 256, SMEM_G>>>(inb, (long long)NN * DIN, web, (long long)HH * DIN,
                                            nullptr, 0, b_emb, HH,
                                            xb, (long long)xs,
                                            nullptr, 0, 0,
                                            2, 1, NN, DIN);

    for (int layer = 0; layer < LL; layer++) {
        float* lstats = zstats + layer * 2 * 2 * HH;
        k_gemm<<<dim3(MB, 8, 2), 256, SMEM_G>>>(xb, (long long)xs,
                                                wcat + (size_t)(layer * 2) * 1024 * HH,
                                                (long long)1024 * HH,
                                                a0, (long long)xs, bls + layer * 2 * HH, HH,
                                                nullptr, 0,
                                                tmpf, (long long)3 * xs, (long long)xs,
                                                2, 0, NN, HH);
        k_agg<<<dim3((NN * 32 + 255) / 256, 2), 256>>>(a0, lstats);
        if (layer < LL - 1) {
            k_bnapply<<<dim3(256, 2), 256>>>(a0, xb, lstats,
                                             gamma + layer * 2 * HH, beta + layer * 2 * HH,
                                             layer > 0);
        } else {
            k_bnpool<<<dim3((NN + 63) / 64, 2), 256>>>(a0, xb, lstats,
                                                       gamma + layer * 2 * HH,
                                                       beta + layer * 2 * HH,
                                                       batch_v, batch_p, zpool);
        }
    }

    k_final<<<1, 1024>>>(W_out, b_out, zpool, zpcnt, out);
}

// round 17
// speedup vs baseline: 1.0723x; 1.0723x over previous
#include <cuda_runtime.h>
#include <cuda_bf16.h>
#include <math.h>
#include <stdint.h>

#define NN   20000
#define EE   320000
#define DIN  128
#define HH   256
#define LL   2
#define GG   32
#define NREL 6

// ---------------- device scratch ----------------
__device__ float g_accb[2 * NN * HH];
__device__ uint8_t g_tmpf[NREL * NN * HH];          // neighbor GEMM outputs (fp8 e4m3)
__device__ __nv_bfloat16 g_xb[2 * NN * HH];         // bf16 feature/residual carrier
__device__ __nv_bfloat16 g_inb[2 * NN * DIN];
__device__ __nv_bfloat16 g_web[2 * HH * DIN];
__device__ __nv_bfloat16 g_wcat[LL * 2 * 1024 * HH];
__device__ float g_blsum[LL * 2 * HH];
__device__ int   g_deg[NREL][NN];
__device__ int   g_rowptr[NREL][NN + 1];
__device__ int   g_cursor[NREL][NN];
__device__ int   g_col[NREL][EE];
struct ZeroBlk {
    float stats[LL * 2 * 2 * HH];
    float pool[2 * GG * HH];
    int   pcnt[2 * GG];
};
__device__ ZeroBlk g_z;
__device__ int g_is64;

// ---------------- helpers ----------------
__device__ __forceinline__ int idx_at(const void* p, long long i, int is64) {
    return is64 ? (int)((const long long*)p)[i] : ((const int*)p)[i];
}
__device__ __forceinline__ uint32_t smem_u32(const void* p) {
    uint32_t a;
    asm("{ .reg .u64 t; cvta.to.shared.u64 t, %1; cvt.u32.u64 %0, t; }" : "=r"(a) : "l"(p));
    return a;
}
__device__ __forceinline__ void ldm_x4(uint32_t* r, uint32_t addr) {
    asm volatile("ldmatrix.sync.aligned.m8n8.x4.shared.b16 {%0,%1,%2,%3}, [%4];"
                 : "=r"(r[0]), "=r"(r[1]), "=r"(r[2]), "=r"(r[3]) : "r"(addr));
}
__device__ __forceinline__ void mma_bf16(float* c, const uint32_t* a, const uint32_t* b) {
    asm volatile("mma.sync.aligned.m16n8k16.row.col.f32.bf16.bf16.f32 "
                 "{%0,%1,%2,%3}, {%4,%5,%6,%7}, {%8,%9}, {%0,%1,%2,%3};"
                 : "+f"(c[0]), "+f"(c[1]), "+f"(c[2]), "+f"(c[3])
                 : "r"(a[0]), "r"(a[1]), "r"(a[2]), "r"(a[3]), "r"(b[0]), "r"(b[1]));
}
__device__ __forceinline__ void cp16(uint32_t dst, const void* src, int nbytes) {
    asm volatile("cp.async.cg.shared.global [%0], [%1], 16, %2;"
                 :: "r"(dst), "l"(src), "r"(nbytes));
}
__device__ __forceinline__ unsigned short pack_e4m3x2(float v0, float v1) {
    unsigned short pk;
    asm("cvt.rn.satfinite.e4m3x2.f32 %0, %1, %2;" : "=h"(pk) : "f"(v1), "f"(v0));
    return pk;
}
__device__ __forceinline__ void addv8(float* s, uint2 v) {
#pragma unroll
    for (int w = 0; w < 2; w++) {
        uint32_t word = w ? v.y : v.x;
#pragma unroll
        for (int h = 0; h < 2; h++) {
            unsigned short pk = (unsigned short)(word >> (h * 16));
            uint32_t f16p;
            asm("cvt.rn.f16x2.e4m3x2 %0, %1;" : "=r"(f16p) : "h"(pk));
            __half2 hh = *reinterpret_cast<__half2*>(&f16p);
            float2 f = __half22float2(hh);
            int bi = w * 4 + h * 2;
            s[bi] += f.x;
            s[bi + 1] += f.y;
        }
    }
}

// ---------------- prep: detect(block0) + weights + input split ----------------
__global__ void k_prep(const unsigned int* __restrict__ e,
                       const float* __restrict__ xv, const float* __restrict__ xp,
                       const float* __restrict__ We, const float* __restrict__ Wl,
                       const float* __restrict__ Wr, const float* __restrict__ bl) {
    const int grp[2][3] = {{0, 1, 3}, {2, 4, 5}};
    int gid = blockIdx.x * blockDim.x + threadIdx.x;

    if (blockIdx.x == 0) {                     // index dtype detection (block 0 only)
        __shared__ int any;
        if (threadIdx.x == 0) any = 0;
        __syncthreads();
        unsigned int v = 0;
        for (int i = threadIdx.x; i < 2048; i += blockDim.x)
            v |= e[(long long)i * 1874 + 1];
        if (v) any = 1;
        __syncthreads();
        if (threadIdx.x == 0) g_is64 = any ? 0 : 1;
    }

    if (gid < 2 * NN * DIN) {                  // input split
        float s = (gid < NN * DIN) ? xv[gid] : xp[gid - NN * DIN];
        g_inb[gid] = __float2bfloat16(s);
    }
    if (gid < 2 * HH * DIN) {                  // emb weights -> [t][n][k]
        int t = gid >> 15, rem = gid & 32767, n = rem >> 7, k = rem & 127;
        g_web[t * HH * DIN + n * DIN + k] =
            __float2bfloat16(We[((long long)t * DIN + k) * HH + n]);
    }
    if (gid < LL * 2 * 1024 * HH) {            // merged layer B
        int lt = gid >> 18, rem = gid & 0x3FFFF, row = rem >> 8, k = rem & 255;
        int layer = lt >> 1, t = lt & 1;
        float w;
        if (row < 256) {
            int n = row;
            const float* W = Wr + (long long)layer * NREL * HH * HH;
            w = W[(long long)grp[t][0] * HH * HH + k * HH + n] +
                W[(long long)grp[t][1] * HH * HH + k * HH + n] +
                W[(long long)grp[t][2] * HH * HH + k * HH + n];
        } else {
            int q = (row - 256) >> 8, n = row & 255;
            int rel = t * 3 + q;
            w = Wl[(((long long)layer * NREL + rel) * HH + k) * HH + n];
        }
        g_wcat[(long long)lt * 1024 * HH + row * HH + k] = __float2bfloat16(w);
    }
    if (gid < LL * 2 * HH) {                   // summed biases
        int lt = gid >> 8, c = gid & 255;
        int layer = lt >> 1, t = lt & 1;
        const float* b = bl + (long long)layer * NREL * HH;
        g_blsum[lt * HH + c] = b[grp[t][0] * HH + c] + b[grp[t][1] * HH + c] +
                               b[grp[t][2] * HH + c];
    }
}

// ---------------- CSR histogram ----------------
__global__ void k_hist(const void* __restrict__ edge) {
    int is64 = g_is64;
    int gid = blockIdx.x * blockDim.x + threadIdx.x;
    if (gid >= NREL * EE) return;
    int r = gid / EE, e = gid - r * EE;
    int dst = idx_at(edge, ((long long)r * 2 + 1) * EE + e, is64);
    atomicAdd(&g_deg[r][dst], 1);
}

// ---------------- CSR scan ----------------
__global__ void __launch_bounds__(1024) k_scan() {
    int r = blockIdx.x;
    const int PER = 20;
    int tid = threadIdx.x;
    int lane = tid & 31, wid = tid >> 5;
    int start = tid * PER;
    int loc[PER];
    int sum = 0;
#pragma unroll
    for (int i = 0; i < PER; i++) {
        int idx = start + i;
        int v = (idx < NN) ? g_deg[r][idx] : 0;
        loc[i] = sum;
        sum += v;
    }
    __shared__ int wsum[32];
    int incl = sum;
#pragma unroll
    for (int o = 1; o < 32; o <<= 1) {
        int x = __shfl_up_sync(0xffffffffu, incl, o);
        if (lane >= o) incl += x;
    }
    if (lane == 31) wsum[wid] = incl;
    __syncthreads();
    if (wid == 0) {
        int v = wsum[lane];
#pragma unroll
        for (int o = 1; o < 32; o <<= 1) {
            int x = __shfl_up_sync(0xffffffffu, v, o);
            if (lane >= o) v += x;
        }
        wsum[lane] = v;
    }
    __syncthreads();
    int prefix = incl - sum + (wid ? wsum[wid - 1] : 0);
#pragma unroll
    for (int i = 0; i < PER; i++) {
        int idx = start + i;
        if (idx < NN) {
            int ex = prefix + loc[i];
            g_rowptr[r][idx] = ex;
            g_cursor[r][idx] = ex;
        }
    }
    if (tid == 1023) g_rowptr[r][NN] = prefix + sum;
}

// ---------------- CSR fill + pooled-count (fused, disjoint ranges) ----------------
__global__ void k_fillp(const void* __restrict__ edge,
                        const void* __restrict__ bv, const void* __restrict__ bp,
                        int* __restrict__ pcnt) {
    int is64 = g_is64;
    int gid = blockIdx.x * blockDim.x + threadIdx.x;
    if (gid < NREL * EE) {
        int r = gid / EE, e = gid - r * EE;
        int src = idx_at(edge, ((long long)r * 2 + 0) * EE + e, is64);
        int dst = idx_at(edge, ((long long)r * 2 + 1) * EE + e, is64);
        int slot = atomicAdd(&g_cursor[r][dst], 1);
        g_col[r][slot] = src;
    } else {
        int q = gid - NREL * EE;
        if (q < 2 * NN) {
            int t = q / NN, i = q - t * NN;
            int g = t ? idx_at(bp, i, is64) : idx_at(bv, i, is64);
            atomicAdd(&pcnt[t * GG + g], 1);
        }
    }
}

// ---------------- HMMA GEMM (bf16x1, BK=64, cp.async double-buffered) ----------------
#define SPAD2 72
#define BUFB (128 * SPAD2 * 2)
#define SMEM_G (4 * BUFB)

__global__ void __launch_bounds__(256, 2) k_gemm(
    const __nv_bfloat16* __restrict__ A0, long long aStr,
    const __nv_bfloat16* __restrict__ B0, long long bStr,
    float* __restrict__ Cf0, long long cfStr,
    const float* __restrict__ bias0, int biasStr,
    __nv_bfloat16* __restrict__ Xb0, long long xbzStr,
    uint8_t* __restrict__ F80, long long f8zStr, long long f8Stride,
    int selfN, int dualOut, int M, int K)
{
    extern __shared__ __nv_bfloat16 sm[];
    int z = blockIdx.z;
    const __nv_bfloat16* A = A0 + (long long)z * aStr;
    const __nv_bfloat16* B = B0 + (long long)z * bStr;
    float* Cf = Cf0 ? Cf0 + (long long)z * cfStr : nullptr;
    const float* bias = bias0 ? bias0 + (long long)z * biasStr : nullptr;
    __nv_bfloat16* Xb = Xb0 ? Xb0 + (long long)z * xbzStr : nullptr;
    uint8_t* F8z = F80 ? F80 + (long long)z * f8zStr : nullptr;

    int tid = threadIdx.x, wid = tid >> 5, lane = tid & 31;
    long long bm = (long long)blockIdx.x * 128;
    int nb = blockIdx.y * 128;
    int wm = (wid & 3) * 32;
    int wn = (wid >> 2) * 64;
    uint32_t sbA = smem_u32(sm);
    uint32_t sbB = sbA + 2 * BUFB;

    float acc[2][8][4];
#pragma unroll
    for (int i = 0; i < 2; i++)
#pragma unroll
        for (int j = 0; j < 8; j++)
#pragma unroll
            for (int q = 0; q < 4; q++) acc[i][j][q] = 0.0f;

    int a_row = (lane & 7) + ((lane >> 3) & 1) * 8;
    int a_col = (lane >> 4) * 8;
    int b_row = lane & 7;
    int b_col = (lane >> 3) * 8;
    int nch = K >> 6;

#define ISSUE_STAGE(c, buf) do {                                                    \
        _Pragma("unroll")                                                           \
        for (int i = tid; i < 1024; i += 256) {                                     \
            int row = i >> 3, seg = (i & 7) << 3;                                   \
            uint32_t so = (buf) * BUFB + (uint32_t)(row * SPAD2 + seg) * 2;         \
            int av = (bm + row < M) ? 16 : 0;                                       \
            const __nv_bfloat16* ga = A + ((bm + row < M) ?                         \
                                           ((bm + row) * K + (c) * 64 + seg) : 0);  \
            const __nv_bfloat16* gb = B + ((long long)(nb + row) * K + (c) * 64 + seg); \
            cp16(sbA + so, ga, av);                                                 \
            cp16(sbB + so, gb, 16);                                                 \
        }                                                                           \
        asm volatile("cp.async.commit_group;");                                     \
    } while (0)

    ISSUE_STAGE(0, 0);
    for (int c = 0; c < nch; c++) {
        if (c + 1 < nch) {
            ISSUE_STAGE(c + 1, (c + 1) & 1);
            asm volatile("cp.async.wait_group 1;");
        } else {
            asm volatile("cp.async.wait_group 0;");
        }
        __syncthreads();

        uint32_t bA = sbA + (c & 1) * BUFB, bB = sbB + (c & 1) * BUFB;
#pragma unroll
        for (int half = 0; half < 2; half++) {
            uint32_t bf[8][4];
#pragma unroll
            for (int nt = 0; nt < 8; nt++)
                ldm_x4(bf[nt], bB + (uint32_t)((wn + nt * 8 + b_row) * SPAD2 +
                                               half * 32 + b_col) * 2);
#pragma unroll
            for (int ks = 0; ks < 2; ks++) {
                uint32_t af[2][4];
#pragma unroll
                for (int mt = 0; mt < 2; mt++)
                    ldm_x4(af[mt], bA + (uint32_t)((wm + mt * 16 + a_row) * SPAD2 +
                                                   half * 32 + ks * 16 + a_col) * 2);
#pragma unroll
                for (int mt = 0; mt < 2; mt++)
#pragma unroll
                    for (int nt = 0; nt < 8; nt++)
                        mma_bf16(acc[mt][nt], af[mt], &bf[nt][ks * 2]);
            }
        }
        __syncthreads();
    }
#undef ISSUE_STAGE

    // ---- epilogue ----
    bool isSelf = (int)blockIdx.y < selfN;
    uint8_t* F8 = (!isSelf && F8z) ? (F8z + (long long)((blockIdx.y >> 1) - 1) * f8Stride) : nullptr;
    int gidr = lane >> 2, tig = lane & 3;
#pragma unroll
    for (int mt = 0; mt < 2; mt++) {
        long long r0 = bm + wm + mt * 16 + gidr;
        long long r1 = r0 + 8;
#pragma unroll
        for (int nt = 0; nt < 8; nt++) {
            int col = (blockIdx.y & 1) * 128 + wn + nt * 8 + tig * 2;
            float b0 = 0.f, b1 = 0.f;
            if (isSelf && bias) { b0 = bias[col]; b1 = bias[col + 1]; }
            if (r0 < M) {
                float v0 = acc[mt][nt][0] + b0, v1 = acc[mt][nt][1] + b1;
                if (isSelf) {
                    if (Cf) *(float2*)&Cf[r0 * 256 + col] = make_float2(v0, v1);
                    if (dualOut) *(__nv_bfloat162*)&Xb[r0 * 256 + col] = __floats2bfloat162_rn(v0, v1);
                } else {
                    *(unsigned short*)&F8[r0 * 256 + col] = pack_e4m3x2(v0, v1);
                }
            }
            if (r1 < M) {
                float v2 = acc[mt][nt][2] + b0, v3 = acc[mt][nt][3] + b1;
                if (isSelf) {
                    if (Cf) *(float2*)&Cf[r1 * 256 + col] = make_float2(v2, v3);
                    if (dualOut) *(__nv_bfloat162*)&Xb[r1 * 256 + col] = __floats2bfloat162_rn(v2, v3);
                } else {
                    *(unsigned short*)&F8[r1 * 256 + col] = pack_e4m3x2(v2, v3);
                }
            }
        }
    }
}

// ---------------- gather-mean aggregation (fp8 source) + fused BN stats ----------------
__global__ void k_agg(float* __restrict__ acc0, float* __restrict__ stats0) {
    __shared__ float bsum[HH], bsq[HH];
    int tid = threadIdx.x;
    int t = blockIdx.y;
    for (int i = tid; i < HH; i += 256) { bsum[i] = 0.f; bsq[i] = 0.f; }
    __syncthreads();

    int w = (blockIdx.x * blockDim.x + tid) >> 5;
    int lane = tid & 31;
    const int grp[2][3] = {{0, 1, 3}, {2, 4, 5}};
    float* acc = acc0 + (long long)t * NN * HH;
    float* stats = stats0 + t * 2 * HH;

    if (w < NN) {
        float s3[8] = {0.f, 0.f, 0.f, 0.f, 0.f, 0.f, 0.f, 0.f};
#pragma unroll
        for (int q = 0; q < 3; q++) {
            int r = grp[t][q];
            int b = g_rowptr[r][w], e = g_rowptr[r][w + 1];
            float s[8] = {0.f, 0.f, 0.f, 0.f, 0.f, 0.f, 0.f, 0.f};
            const uint2* base = (const uint2*)(g_tmpf + (long long)r * NN * HH);
            for (int j0 = b; j0 < e; j0 += 32) {
                int n = min(32, e - j0);
                int myc = (lane < n) ? g_col[r][j0 + lane] : 0;
                int k = 0;
                for (; k + 3 < n; k += 4) {
                    int c0 = __shfl_sync(0xffffffffu, myc, k);
                    int c1 = __shfl_sync(0xffffffffu, myc, k + 1);
                    int c2 = __shfl_sync(0xffffffffu, myc, k + 2);
                    int c3 = __shfl_sync(0xffffffffu, myc, k + 3);
                    uint2 v0 = base[(long long)c0 * 32 + lane];
                    uint2 v1 = base[(long long)c1 * 32 + lane];
                    uint2 v2 = base[(long long)c2 * 32 + lane];
                    uint2 v3 = base[(long long)c3 * 32 + lane];
                    addv8(s, v0); addv8(s, v1); addv8(s, v2); addv8(s, v3);
                }
                for (; k < n; k++) {
                    int c0 = __shfl_sync(0xffffffffu, myc, k);
                    uint2 v0 = base[(long long)c0 * 32 + lane];
                    addv8(s, v0);
                }
            }
            float inv = (e > b) ? 1.0f / (float)(e - b) : 0.0f;
#pragma unroll
            for (int u = 0; u < 8; u++) s3[u] = fmaf(s[u], inv, s3[u]);
        }
        float4* arow = (float4*)(acc + (long long)w * HH + lane * 8);
        float4 o0 = arow[0], o1 = arow[1];
        float fin[8] = {o0.x + s3[0], o0.y + s3[1], o0.z + s3[2], o0.w + s3[3],
                        o1.x + s3[4], o1.y + s3[5], o1.z + s3[6], o1.w + s3[7]};
        arow[0] = make_float4(fin[0], fin[1], fin[2], fin[3]);
        arow[1] = make_float4(fin[4], fin[5], fin[6], fin[7]);
#pragma unroll
        for (int u = 0; u < 8; u++) {
            atomicAdd(&bsum[lane * 8 + u], fin[u]);
            atomicAdd(&bsq[lane * 8 + u], fin[u] * fin[u]);
        }
    }
    __syncthreads();
    for (int i = tid; i < HH; i += 256) {
        atomicAdd(&stats[i], bsum[i]);
        atomicAdd(&stats[HH + i], bsq[i]);
    }
}

// ---------------- batchnorm apply (non-final layers, bf16 carrier) ----------------
__global__ void k_bnapply(const float* __restrict__ acc0,
                          __nv_bfloat16* __restrict__ xb0,
                          const float* __restrict__ st0, const float* __restrict__ gamma0,
                          const float* __restrict__ beta0, int resid) {
    int t = blockIdx.y;
    long long off = (long long)t * NN * HH;
    const float* acc = acc0 + off;
    __nv_bfloat16* xb = xb0 + off;
    const float* st = st0 + t * 2 * HH;
    const float* gamma = gamma0 + t * HH;
    const float* beta  = beta0 + t * HH;
    int c = threadIdx.x;
    float meanA = st[c] * (1.0f / NN);
    float varA  = st[HH + c] * (1.0f / NN) - meanA * meanA;
    float varX  = varA * (1.0f / 9.0f);
    float rs    = rsqrtf(varX + 1e-5f);
    float scale = gamma[c] * rs * (1.0f / 3.0f);
    float shift = beta[c] - meanA * scale;
    for (int r = blockIdx.x; r < NN; r += gridDim.x) {
        long long i = (long long)r * HH + c;
        float y = fmaxf(fmaf(acc[i], scale, shift), 0.0f);
        float xn = resid ? (__bfloat162float(xb[i]) + y) : y;
        xb[i] = __float2bfloat16(xn);
    }
}

// ---------------- final layer: BN + residual(bf16) + mean pool, fused ----------------
__global__ void k_bnpool(const float* __restrict__ acc0, const __nv_bfloat16* __restrict__ xb0,
                         const float* __restrict__ st0, const float* __restrict__ gamma0,
                         const float* __restrict__ beta0,
                         const void* __restrict__ bv, const void* __restrict__ bp,
                         float* __restrict__ pool0) {
    int is64 = g_is64;
    int t = blockIdx.y;
    long long off = (long long)t * NN * HH;
    const float* acc = acc0 + off;
    const __nv_bfloat16* xb = xb0 + off;
    const float* st = st0 + t * 2 * HH;
    const void* batch = t ? bp : bv;
    float* pool = pool0 + t * GG * HH;
    int c = threadIdx.x;
    float meanA = st[c] * (1.0f / NN);
    float varA  = st[HH + c] * (1.0f / NN) - meanA * meanA;
    float rs    = rsqrtf(varA * (1.0f / 9.0f) + 1e-5f);
    float scale = gamma0[t * HH + c] * rs * (1.0f / 3.0f);
    float shift = beta0[t * HH + c] - meanA * scale;

    int r0 = blockIdx.x * 64;
    int r1 = min(r0 + 64, NN);
    float local = 0.f;
    int gprev = -1;
    for (int r = r0; r < r1; r++) {
        int g = idx_at(batch, r, is64);
        if (g != gprev) {
            if (gprev >= 0) atomicAdd(&pool[gprev * HH + c], local);
            local = 0.f;
            gprev = g;
        }
        long long i = (long long)r * HH + c;
        float y = fmaxf(fmaf(acc[i], scale, shift), 0.0f);
        local += __bfloat162float(xb[i]) + y;
    }
    if (gprev >= 0) atomicAdd(&pool[gprev * HH + c], local);
}

// ---------------- head ----------------
__global__ void k_final(const float* __restrict__ Wo, const float* __restrict__ bo,
                        const float* __restrict__ pool, const int* __restrict__ pcnt,
                        float* __restrict__ out) {
    int g = threadIdx.x >> 5, lane = threadIdx.x & 31;
    if (g >= GG) return;
    float cv = (float)max(pcnt[g], 1);
    float cp = (float)max(pcnt[GG + g], 1);
    float s = 0.f;
    for (int c = lane; c < HH; c += 32)
        s += pool[g * HH + c] / cv * Wo[c] + pool[GG * HH + g * HH + c] / cp * Wo[HH + c];
#pragma unroll
    for (int off = 16; off; off >>= 1) s += __shfl_down_sync(0xffffffffu, s, off);
    if (lane == 0) out[g] = 1.0f / (1.0f + expf(-(s + bo[0])));
}

// ---------------- launcher ----------------
extern "C" void kernel_launch(void* const* d_in, const int* in_sizes, int n_in,
                              void* d_out, int out_size) {
    const float* x_vuln  = (const float*)d_in[0];
    const float* x_patch = (const float*)d_in[1];
    const float* W_emb   = (const float*)d_in[2];
    const float* b_emb   = (const float*)d_in[3];
    const float* W_l     = (const float*)d_in[4];
    const float* b_l     = (const float*)d_in[5];
    const float* W_r     = (const float*)d_in[6];
    const float* gamma   = (const float*)d_in[7];
    const float* beta    = (const float*)d_in[8];
    const float* W_out   = (const float*)d_in[9];
    const float* b_out   = (const float*)d_in[10];
    const void* edge     = d_in[11];
    const void* batch_v  = d_in[12];
    const void* batch_p  = d_in[13];
    float* out = (float*)d_out;

    void* p;
    cudaGetSymbolAddress(&p, g_accb);  float* a0 = (float*)p;
    cudaGetSymbolAddress(&p, g_tmpf);  uint8_t* tmpf = (uint8_t*)p;
    cudaGetSymbolAddress(&p, g_xb);    __nv_bfloat16* xb = (__nv_bfloat16*)p;
    cudaGetSymbolAddress(&p, g_inb);   __nv_bfloat16* inb = (__nv_bfloat16*)p;
    cudaGetSymbolAddress(&p, g_web);   __nv_bfloat16* web = (__nv_bfloat16*)p;
    cudaGetSymbolAddress(&p, g_wcat);  __nv_bfloat16* wcat = (__nv_bfloat16*)p;
    cudaGetSymbolAddress(&p, g_blsum); float* bls = (float*)p;
    cudaGetSymbolAddress(&p, g_deg);   void* degp = p;
    cudaGetSymbolAddress(&p, g_z);     void* zbase = p;
    float* zstats = (float*)zbase;
    float* zpool  = zstats + LL * 2 * 2 * HH;
    int*   zpcnt  = (int*)(zpool + 2 * GG * HH);

    cudaFuncSetAttribute(k_gemm, cudaFuncAttributeMaxDynamicSharedMemorySize, SMEM_G);

    cudaMemsetAsync(degp, 0, sizeof(int) * NREL * NN, 0);
    cudaMemsetAsync(zbase, 0, sizeof(ZeroBlk), 0);

    // prep (detect + weights + split), hist, scan, fill+pcnt
    k_prep<<<20000, 256>>>((const unsigned int*)edge, x_vuln, x_patch, W_emb, W_l, W_r, b_l);
    k_hist<<<(NREL * EE + 255) / 256, 256>>>(edge);
    k_scan<<<NREL, 1024>>>();
    k_fillp<<<(NREL * EE + 2 * NN + 255) / 256, 256>>>(edge, batch_v, batch_p, zpcnt);

    const int MB = (NN + 127) / 128;
    size_t xs = (size_t)NN * HH;
    // embedding GEMMs (K=128): bf16 xb output only
    k_gemm<<<dim3(MB, 2, 2), 256, SMEM_G>>>(inb, (long long)NN * DIN, web, (long long)HH * DIN,
                                            nullptr, 0, b_emb, HH,
                                            xb, (long long)xs,
                                            nullptr, 0, 0,
                                            2, 1, NN, DIN);

    for (int layer = 0; layer < LL; layer++) {
        float* lstats = zstats + layer * 2 * 2 * HH;
        k_gemm<<<dim3(MB, 8, 2), 256, SMEM_G>>>(xb, (long long)xs,
                                                wcat + (size_t)(layer * 2) * 1024 * HH,
                                                (long long)1024 * HH,
                                                a0, (long long)xs, bls + layer * 2 * HH, HH,
                                                nullptr, 0,
                                                tmpf, (long long)3 * xs, (long long)xs,
                                                2, 0, NN, HH);
        k_agg<<<dim3((NN * 32 + 255) / 256, 2), 256>>>(a0, lstats);
        if (layer < LL - 1) {
            k_bnapply<<<dim3(256, 2), 256>>>(a0, xb, lstats,
                                             gamma + layer * 2 * HH, beta + layer * 2 * HH,
                                             layer > 0);
        } else {
            k_bnpool<<<dim3((NN + 63) / 64, 2), 256>>>(a0, xb, lstats,
                                                       gamma + layer * 2 * HH,
                                                       beta + layer * 2 * HH,
                                                       batch_v, batch_p, zpool);
        }
    }

    k_final<<<1, 1024>>>(W_out, b_out, zpool, zpcnt, out);
}